// round 6
// baseline (speedup 1.0000x reference)
#include <cuda_runtime.h>
#include <cstdint>
#include <math.h>

#define Bq 2
#define Sq 2048
#define Dq 1024
#define Hq 16
#define HDq 64
#define Fq 4096
#define NTOK (Bq*Sq)   // 4096

// ---- scratch (allocation-free) ----
__device__ float g_h  [NTOK*Dq];
__device__ float g_q  [NTOK*Dq];
__device__ float g_k  [NTOK*Dq];
__device__ float g_v  [NTOK*Dq];
__device__ float g_att[NTOK*Dq];
__device__ float g_x2 [NTOK*Dq];
__device__ float g_h2 [NTOK*Dq];
__device__ float g_mlp[NTOK*Fq];
// tf32-rounded weights
__device__ float g_wq[Dq*Dq];
__device__ float g_wk[Dq*Dq];
__device__ float g_wv[Dq*Dq];
__device__ float g_wo[Dq*Dq];
__device__ float g_w1[Fq*Dq];
__device__ float g_w2[Dq*Fq];

__device__ __forceinline__ uint32_t tf32r(float x) {
    uint32_t u;
    asm("cvt.rna.tf32.f32 %0, %1;" : "=r"(u) : "f"(x));
    return u;
}
__device__ __forceinline__ float tf32f(float x) {
    return __uint_as_float(tf32r(x));
}
__device__ __forceinline__ uint32_t smem_u32(const void* p) {
    uint32_t a;
    asm("{ .reg .u64 t; cvta.to.shared.u64 t, %1; cvt.u32.u64 %0, t; }" : "=r"(a) : "l"(p));
    return a;
}
__device__ __forceinline__ void cp_async16(uint32_t dst, const void* src) {
    asm volatile("cp.async.ca.shared.global [%0], [%1], 16;" :: "r"(dst), "l"(src));
}
__device__ __forceinline__ void cp_commit() {
    asm volatile("cp.async.commit_group;" ::: "memory");
}
template <int N>
__device__ __forceinline__ void cp_wait() {
    asm volatile("cp.async.wait_group %0;" :: "n"(N) : "memory");
}
__device__ __forceinline__ void mma_tf32(float* c, const uint32_t* a, const uint32_t* b) {
    asm volatile(
        "mma.sync.aligned.m16n8k8.row.col.f32.tf32.tf32.f32 "
        "{%0,%1,%2,%3}, {%4,%5,%6,%7}, {%8,%9}, {%0,%1,%2,%3};"
        : "+f"(c[0]), "+f"(c[1]), "+f"(c[2]), "+f"(c[3])
        : "r"(a[0]), "r"(a[1]), "r"(a[2]), "r"(a[3]),
          "r"(b[0]), "r"(b[1]));
}

// ================= weight tf32 pre-round =================
// 12M floats total: Wq,Wk,Wv,Wo (1M each), W1,W2 (4M each). float4-grain.
__global__ void wcvt_kernel(const float* __restrict__ wq, const float* __restrict__ wk,
                            const float* __restrict__ wv, const float* __restrict__ wo,
                            const float* __restrict__ w1, const float* __restrict__ w2,
                            float* oq, float* ok, float* ov, float* oo,
                            float* o1, float* o2) {
    const int Qk = Dq * Dq / 4;  // 256K float4 per 1M-matrix
    int i4 = blockIdx.x * 256 + threadIdx.x;
    const float* s;
    float* d;
    int off;
    if (i4 < Qk)            { s = wq; d = oq; off = i4; }
    else if (i4 < 2 * Qk)   { s = wk; d = ok; off = i4 - Qk; }
    else if (i4 < 3 * Qk)   { s = wv; d = ov; off = i4 - 2 * Qk; }
    else if (i4 < 4 * Qk)   { s = wo; d = oo; off = i4 - 3 * Qk; }
    else if (i4 < 8 * Qk)   { s = w1; d = o1; off = i4 - 4 * Qk; }
    else                    { s = w2; d = o2; off = i4 - 8 * Qk; }
    float4 v = ((const float4*)s)[off];
    v.x = tf32f(v.x); v.y = tf32f(v.y); v.z = tf32f(v.z); v.w = tf32f(v.w);
    ((float4*)d)[off] = v;
}

// ================= LayerNorm (tf32-rounded output) =================
__global__ void ln_kernel(const float* __restrict__ x,
                          const float* __restrict__ g,
                          const float* __restrict__ b,
                          float* __restrict__ out) {
    __shared__ float sm[32];
    int row = blockIdx.x;
    const float* xr = x + (size_t)row * Dq;
    float* outr = out + (size_t)row * Dq;
    float4 v4 = *(const float4*)(xr + threadIdx.x * 4);
    float sum = v4.x + v4.y + v4.z + v4.w;
    int lane = threadIdx.x & 31, wid = threadIdx.x >> 5;
#pragma unroll
    for (int o = 16; o > 0; o >>= 1) sum += __shfl_xor_sync(0xffffffffu, sum, o);
    if (lane == 0) sm[wid] = sum;
    __syncthreads();
    float s0 = (threadIdx.x < 8) ? sm[threadIdx.x] : 0.f;
    if (wid == 0) {
#pragma unroll
        for (int o = 4; o > 0; o >>= 1) s0 += __shfl_xor_sync(0xffffffffu, s0, o);
        if (lane == 0) sm[0] = s0;
    }
    __syncthreads();
    float mu = sm[0] * (1.0f / Dq);
    __syncthreads();
    float d0 = v4.x - mu, d1 = v4.y - mu, d2 = v4.z - mu, d3 = v4.w - mu;
    float vs = d0 * d0 + d1 * d1 + d2 * d2 + d3 * d3;
#pragma unroll
    for (int o = 16; o > 0; o >>= 1) vs += __shfl_xor_sync(0xffffffffu, vs, o);
    if (lane == 0) sm[wid] = vs;
    __syncthreads();
    float v0 = (threadIdx.x < 8) ? sm[threadIdx.x] : 0.f;
    if (wid == 0) {
#pragma unroll
        for (int o = 4; o > 0; o >>= 1) v0 += __shfl_xor_sync(0xffffffffu, v0, o);
        if (lane == 0) sm[0] = v0;
    }
    __syncthreads();
    float rstd = rsqrtf(sm[0] * (1.0f / Dq) + 1e-5f);
    int c = threadIdx.x * 4;
    float4 gg = *(const float4*)(g + c);
    float4 bb = *(const float4*)(b + c);
    float4 o;
    o.x = tf32f(d0 * rstd * gg.x + bb.x);
    o.y = tf32f(d1 * rstd * gg.y + bb.y);
    o.z = tf32f(d2 * rstd * gg.z + bb.z);
    o.w = tf32f(d3 * rstd * gg.w + bb.w);
    *(float4*)(outr + c) = o;
}

// ================= tf32 mma GEMM body (3-stage cp.async) =================
// Inputs already tf32-rounded. Tile 128x128, K-chunk 32, 8 warps 2x4.
// EPI: 0 = bias + round tf32, 1 = bias + gelu + round tf32, 2 = bias + residual (f32)
#define STRIDE 36
#define STAGE_FLOATS (2 * 128 * STRIDE)         // 9216 floats
#define STAGE_BYTES  (STAGE_FLOATS * 4)         // 36864 B
#define GEMM_SMEM    (3 * STAGE_BYTES)          // 110592 B

template <int EPI>
__device__ __forceinline__ void gemm_body(
    const float* __restrict__ A, const float* __restrict__ W,
    const float* __restrict__ bias, const float* __restrict__ res,
    float* __restrict__ C, int N, int K, int bm, int bn) {
    extern __shared__ uint32_t smem[];
    const uint32_t smb = smem_u32(smem);
    const int tid = threadIdx.x;
    const int wid = tid >> 5, lane = tid & 31;
    const int warp_m = wid >> 2, warp_n = wid & 3;

    float acc[4][4][4];
#pragma unroll
    for (int i = 0; i < 4; i++)
#pragma unroll
        for (int j = 0; j < 4; j++)
#pragma unroll
            for (int u = 0; u < 4; u++) acc[i][j][u] = 0.f;

    const int lc = (tid & 7) * 4;
    const int aBase = (warp_m * 64 + (lane >> 2)) * STRIDE + (lane & 3);
    const int bBase = 128 * STRIDE + (warp_n * 32 + (lane >> 2)) * STRIDE + (lane & 3);
    const int nk = K >> 5;

    uint32_t dA[4], dW[4];
    const float* srcA[4];
    const float* srcW[4];
#pragma unroll
    for (int i = 0; i < 4; i++) {
        int idx = tid + i * 256;
        int r = idx >> 3;
        dA[i] = smb + (uint32_t)(r * STRIDE + lc) * 4u;
        dW[i] = smb + (uint32_t)((128 + r) * STRIDE + lc) * 4u;
        srcA[i] = A + (size_t)(bm + r) * K + lc;
        srcW[i] = W + (size_t)(bn + r) * K + lc;
    }

    // prologue: stages 0, 1
#pragma unroll
    for (int s = 0; s < 2; s++) {
        uint32_t so = (uint32_t)(s * STAGE_BYTES);
#pragma unroll
        for (int i = 0; i < 4; i++) {
            cp_async16(dA[i] + so, srcA[i] + s * 32);
            cp_async16(dW[i] + so, srcW[i] + s * 32);
        }
        cp_commit();
    }

    int ld_stage = 2;   // stage slot for next prefetch
    int cp_stage = 0;   // stage slot being computed
    for (int kt = 0; kt < nk; kt++) {
        cp_wait<1>();
        __syncthreads();
        if (kt + 2 < nk) {
            uint32_t so = (uint32_t)(ld_stage * STAGE_BYTES);
            const int koff = (kt + 2) * 32;
#pragma unroll
            for (int i = 0; i < 4; i++) {
                cp_async16(dA[i] + so, srcA[i] + koff);
                cp_async16(dW[i] + so, srcW[i] + koff);
            }
        }
        cp_commit();
        if (++ld_stage == 3) ld_stage = 0;

        const uint32_t* st = smem + cp_stage * STAGE_FLOATS;
        if (++cp_stage == 3) cp_stage = 0;
#pragma unroll
        for (int ks = 0; ks < 4; ks++) {
            uint32_t af[4][4], bf[4][2];
#pragma unroll
            for (int mt = 0; mt < 4; mt++) {
                const uint32_t* p = st + aBase + mt * (16 * STRIDE) + ks * 8;
                af[mt][0] = p[0];
                af[mt][1] = p[8 * STRIDE];
                af[mt][2] = p[4];
                af[mt][3] = p[8 * STRIDE + 4];
            }
#pragma unroll
            for (int nt = 0; nt < 4; nt++) {
                const uint32_t* p = st + bBase + nt * (8 * STRIDE) + ks * 8;
                bf[nt][0] = p[0];
                bf[nt][1] = p[4];
            }
#pragma unroll
            for (int mt = 0; mt < 4; mt++)
#pragma unroll
                for (int nt = 0; nt < 4; nt++)
                    mma_tf32(acc[mt][nt], af[mt], bf[nt]);
        }
    }

    // epilogue
#pragma unroll
    for (int mt = 0; mt < 4; mt++) {
#pragma unroll
        for (int nt = 0; nt < 4; nt++) {
            int row = bm + warp_m * 64 + mt * 16 + (lane >> 2);
            int col = bn + warp_n * 32 + nt * 8 + 2 * (lane & 3);
#pragma unroll
            for (int half = 0; half < 2; half++) {
                int r = row + half * 8;
                float v0 = acc[mt][nt][half * 2 + 0] + bias[col];
                float v1 = acc[mt][nt][half * 2 + 1] + bias[col + 1];
                if (EPI == 0) {
                    v0 = tf32f(v0);
                    v1 = tf32f(v1);
                }
                if (EPI == 1) {
                    float z0 = 0.7978845608028654f * (v0 + 0.044715f * v0 * v0 * v0);
                    float z1 = 0.7978845608028654f * (v1 + 0.044715f * v1 * v1 * v1);
                    v0 = tf32f(v0 / (1.f + __expf(-2.f * z0)));
                    v1 = tf32f(v1 / (1.f + __expf(-2.f * z1)));
                }
                if (EPI == 2) {
                    v0 += res[(size_t)r * N + col];
                    v1 += res[(size_t)r * N + col + 1];
                }
                float2 o; o.x = v0; o.y = v1;
                *(float2*)(C + (size_t)r * N + col) = o;
            }
        }
    }
}

template <int EPI>
__global__ void __launch_bounds__(256, 2)
gemm_mma(const float* __restrict__ A, const float* __restrict__ W,
         const float* __restrict__ bias, const float* __restrict__ res,
         float* __restrict__ C, int N, int K) {
    gemm_body<EPI>(A, W, bias, res, C, N, K, blockIdx.y * 128, blockIdx.x * 128);
}

// fused QKV: grid.x = 24 (3 matrices x 8 n-tiles)
__global__ void __launch_bounds__(256, 2)
qkv_mma(const float* __restrict__ h,
        const float* __restrict__ wq, const float* __restrict__ wk, const float* __restrict__ wv,
        const float* __restrict__ bq, const float* __restrict__ bk, const float* __restrict__ bv,
        float* __restrict__ q, float* __restrict__ k, float* __restrict__ v) {
    int sel = blockIdx.x >> 3;
    int bn = (blockIdx.x & 7) * 128;
    const float* W = (sel == 0) ? wq : (sel == 1) ? wk : wv;
    const float* bias = (sel == 0) ? bq : (sel == 1) ? bk : bv;
    float* C = (sel == 0) ? q : (sel == 1) ? k : v;
    gemm_body<0>(h, W, bias, nullptr, C, Dq, Dq, blockIdx.y * 128, bn);
}

// ================= tf32 mma flash attention =================
// inputs q,k,v already tf32-rounded; output rounded (feeds Wo GEMM).
#define KS_STR 68
#define VS_STR 72
#define PS_STR 68
#define ATT_SMEM ((64*KS_STR + 64*VS_STR + 8*16*PS_STR) * 4)

__global__ void __launch_bounds__(256, 1)
attn_mma(const float* __restrict__ q, const float* __restrict__ k,
         const float* __restrict__ v, float* __restrict__ out) {
    extern __shared__ uint32_t sm[];
    uint32_t* Ksm = sm;
    uint32_t* Vsm = sm + 64 * KS_STR;
    uint32_t* Psm = Vsm + 64 * VS_STR;
    const int tid = threadIdx.x, wid = tid >> 5, lane = tid & 31;
    const int g = lane >> 2, t = lane & 3;
    const int bh = blockIdx.x, b = bh >> 4, h = bh & 15;
    const int q0 = blockIdx.y * 128 + wid * 16;
    uint32_t* Pw = Psm + wid * 16 * PS_STR;

    uint32_t aq[8][4];
    const float* qb = q + ((size_t)(b * Sq + q0)) * Dq + h * HDq;
#pragma unroll
    for (int ks = 0; ks < 8; ks++) {
        // q pre-rounded; *0.125f is exact (power of 2), still tf32-valid
        aq[ks][0] = __float_as_uint(qb[(size_t)g * Dq + ks * 8 + t] * 0.125f);
        aq[ks][1] = __float_as_uint(qb[(size_t)(g + 8) * Dq + ks * 8 + t] * 0.125f);
        aq[ks][2] = __float_as_uint(qb[(size_t)g * Dq + ks * 8 + t + 4] * 0.125f);
        aq[ks][3] = __float_as_uint(qb[(size_t)(g + 8) * Dq + ks * 8 + t + 4] * 0.125f);
    }
    float o[8][4];
#pragma unroll
    for (int nt = 0; nt < 8; nt++)
#pragma unroll
        for (int u = 0; u < 4; u++) o[nt][u] = 0.f;
    float m0 = -1e30f, m1 = -1e30f, l0 = 0.f, l1 = 0.f;

    for (int kt = 0; kt < Sq / 64; kt++) {
        const float* kb = k + ((size_t)(b * Sq + kt * 64)) * Dq + h * HDq;
        const float* vb = v + ((size_t)(b * Sq + kt * 64)) * Dq + h * HDq;
#pragma unroll
        for (int i = 0; i < 4; i++) {
            int idx = tid + i * 256;
            int r = idx >> 4, c = (idx & 15) * 4;
            *(uint4*)(Ksm + r * KS_STR + c) = *(const uint4*)(kb + (size_t)r * Dq + c);
            *(uint4*)(Vsm + r * VS_STR + c) = *(const uint4*)(vb + (size_t)r * Dq + c);
        }
        __syncthreads();

        float s[8][4];
#pragma unroll
        for (int nt = 0; nt < 8; nt++)
#pragma unroll
            for (int u = 0; u < 4; u++) s[nt][u] = 0.f;
#pragma unroll
        for (int ks = 0; ks < 8; ks++) {
#pragma unroll
            for (int nt = 0; nt < 8; nt++) {
                uint32_t bf[2];
                bf[0] = Ksm[(nt * 8 + g) * KS_STR + ks * 8 + t];
                bf[1] = Ksm[(nt * 8 + g) * KS_STR + ks * 8 + t + 4];
                mma_tf32(s[nt], aq[ks], bf);
            }
        }

        float mx0 = -1e30f, mx1 = -1e30f;
#pragma unroll
        for (int nt = 0; nt < 8; nt++) {
            mx0 = fmaxf(mx0, fmaxf(s[nt][0], s[nt][1]));
            mx1 = fmaxf(mx1, fmaxf(s[nt][2], s[nt][3]));
        }
        mx0 = fmaxf(mx0, __shfl_xor_sync(0xffffffffu, mx0, 1));
        mx0 = fmaxf(mx0, __shfl_xor_sync(0xffffffffu, mx0, 2));
        mx1 = fmaxf(mx1, __shfl_xor_sync(0xffffffffu, mx1, 1));
        mx1 = fmaxf(mx1, __shfl_xor_sync(0xffffffffu, mx1, 2));
        float nm0 = fmaxf(m0, mx0), nm1 = fmaxf(m1, mx1);
        float c0 = __expf(m0 - nm0), c1 = __expf(m1 - nm1);
        float sum0 = 0.f, sum1 = 0.f;
#pragma unroll
        for (int nt = 0; nt < 8; nt++) {
            s[nt][0] = __expf(s[nt][0] - nm0);
            s[nt][1] = __expf(s[nt][1] - nm0);
            s[nt][2] = __expf(s[nt][2] - nm1);
            s[nt][3] = __expf(s[nt][3] - nm1);
            sum0 += s[nt][0] + s[nt][1];
            sum1 += s[nt][2] + s[nt][3];
        }
        sum0 += __shfl_xor_sync(0xffffffffu, sum0, 1);
        sum0 += __shfl_xor_sync(0xffffffffu, sum0, 2);
        sum1 += __shfl_xor_sync(0xffffffffu, sum1, 1);
        sum1 += __shfl_xor_sync(0xffffffffu, sum1, 2);
        l0 = l0 * c0 + sum0;
        l1 = l1 * c1 + sum1;
#pragma unroll
        for (int nt = 0; nt < 8; nt++) {
            o[nt][0] *= c0; o[nt][1] *= c0;
            o[nt][2] *= c1; o[nt][3] *= c1;
        }
        m0 = nm0; m1 = nm1;

#pragma unroll
        for (int nt = 0; nt < 8; nt++) {
            uint2 p0; p0.x = tf32r(s[nt][0]); p0.y = tf32r(s[nt][1]);
            *(uint2*)(Pw + g * PS_STR + nt * 8 + 2 * t) = p0;
            uint2 p1; p1.x = tf32r(s[nt][2]); p1.y = tf32r(s[nt][3]);
            *(uint2*)(Pw + (g + 8) * PS_STR + nt * 8 + 2 * t) = p1;
        }
        __syncwarp();

#pragma unroll
        for (int ks = 0; ks < 8; ks++) {
            uint32_t ap[4];
            ap[0] = Pw[g * PS_STR + ks * 8 + t];
            ap[1] = Pw[(g + 8) * PS_STR + ks * 8 + t];
            ap[2] = Pw[g * PS_STR + ks * 8 + t + 4];
            ap[3] = Pw[(g + 8) * PS_STR + ks * 8 + t + 4];
#pragma unroll
            for (int nt = 0; nt < 8; nt++) {
                uint32_t bf[2];
                bf[0] = Vsm[(ks * 8 + t) * VS_STR + nt * 8 + g];
                bf[1] = Vsm[(ks * 8 + t + 4) * VS_STR + nt * 8 + g];
                mma_tf32(o[nt], ap, bf);
            }
        }
        __syncthreads();
    }

    float i0 = 1.f / l0, i1 = 1.f / l1;
    float* ob = out + ((size_t)(b * Sq + q0)) * Dq + h * HDq;
#pragma unroll
    for (int nt = 0; nt < 8; nt++) {
        float2 w0; w0.x = tf32f(o[nt][0] * i0); w0.y = tf32f(o[nt][1] * i0);
        *(float2*)(ob + (size_t)g * Dq + nt * 8 + 2 * t) = w0;
        float2 w1; w1.x = tf32f(o[nt][2] * i1); w1.y = tf32f(o[nt][3] * i1);
        *(float2*)(ob + (size_t)(g + 8) * Dq + nt * 8 + 2 * t) = w1;
    }
}

// ================= launch =================
extern "C" void kernel_launch(void* const* d_in, const int* in_sizes, int n_in,
                              void* d_out, int out_size) {
    const float* x     = (const float*)d_in[0];
    const float* Wq    = (const float*)d_in[1];
    const float* bq    = (const float*)d_in[2];
    const float* Wk    = (const float*)d_in[3];
    const float* bk    = (const float*)d_in[4];
    const float* Wv    = (const float*)d_in[5];
    const float* bv    = (const float*)d_in[6];
    const float* Wo    = (const float*)d_in[7];
    const float* bo    = (const float*)d_in[8];
    const float* ln1_g = (const float*)d_in[9];
    const float* ln1_b = (const float*)d_in[10];
    const float* W1    = (const float*)d_in[11];
    const float* b1    = (const float*)d_in[12];
    const float* W2    = (const float*)d_in[13];
    const float* b2    = (const float*)d_in[14];
    const float* ln2_g = (const float*)d_in[15];
    const float* ln2_b = (const float*)d_in[16];
    float* out = (float*)d_out;

    float *h, *q, *k, *v, *att, *x2, *h2, *mlp;
    float *wq, *wk, *wv, *wo, *w1, *w2;
    cudaGetSymbolAddress((void**)&h,   g_h);
    cudaGetSymbolAddress((void**)&q,   g_q);
    cudaGetSymbolAddress((void**)&k,   g_k);
    cudaGetSymbolAddress((void**)&v,   g_v);
    cudaGetSymbolAddress((void**)&att, g_att);
    cudaGetSymbolAddress((void**)&x2,  g_x2);
    cudaGetSymbolAddress((void**)&h2,  g_h2);
    cudaGetSymbolAddress((void**)&mlp, g_mlp);
    cudaGetSymbolAddress((void**)&wq,  g_wq);
    cudaGetSymbolAddress((void**)&wk,  g_wk);
    cudaGetSymbolAddress((void**)&wv,  g_wv);
    cudaGetSymbolAddress((void**)&wo,  g_wo);
    cudaGetSymbolAddress((void**)&w1,  g_w1);
    cudaGetSymbolAddress((void**)&w2,  g_w2);

    cudaFuncSetAttribute(gemm_mma<1>, cudaFuncAttributeMaxDynamicSharedMemorySize, GEMM_SMEM);
    cudaFuncSetAttribute(gemm_mma<2>, cudaFuncAttributeMaxDynamicSharedMemorySize, GEMM_SMEM);
    cudaFuncSetAttribute(qkv_mma, cudaFuncAttributeMaxDynamicSharedMemorySize, GEMM_SMEM);
    cudaFuncSetAttribute(attn_mma, cudaFuncAttributeMaxDynamicSharedMemorySize, ATT_SMEM);

    // 0) round weights to tf32 once per call
    const int WTOT4 = (4 * Dq * Dq + 2 * Fq * Dq) / 4;  // 3M float4
    wcvt_kernel<<<WTOT4 / 256, 256>>>(Wq, Wk, Wv, Wo, W1, W2, wq, wk, wv, wo, w1, w2);

    // 1) LN1 (rounded output)
    ln_kernel<<<NTOK, 256>>>(x, ln1_g, ln1_b, h);

    // 2) fused QKV
    dim3 gq(24, NTOK / 128);
    qkv_mma<<<gq, 256, GEMM_SMEM>>>(h, wq, wk, wv, bq, bk, bv, q, k, v);

    // 3) attention
    dim3 gattn(Bq * Hq, Sq / 128);
    attn_mma<<<gattn, 256, ATT_SMEM>>>(q, k, v, att);

    // 4) output projection + residual
    dim3 go(Dq / 128, NTOK / 128);
    gemm_mma<2><<<go, 256, GEMM_SMEM>>>(att, wo, bo, x, x2, Dq, Dq);

    // 5) LN2 (rounded output)
    ln_kernel<<<NTOK, 256>>>(x2, ln2_g, ln2_b, h2);

    // 6) MLP up + gelu (rounded output)
    dim3 g1(Fq / 128, NTOK / 128);
    gemm_mma<1><<<g1, 256, GEMM_SMEM>>>(h2, w1, b1, nullptr, mlp, Fq, Dq);

    // 7) MLP down + residual -> out
    dim3 g2(Dq / 128, NTOK / 128);
    gemm_mma<2><<<g2, 256, GEMM_SMEM>>>(mlp, w2, b2, x2, out, Dq, Fq);
}

// round 7
// speedup vs baseline: 1.1107x; 1.1107x over previous
#include <cuda_runtime.h>
#include <cstdint>
#include <math.h>

#define Bq 2
#define Sq 2048
#define Dq 1024
#define Hq 16
#define HDq 64
#define Fq 4096
#define NTOK (Bq*Sq)   // 4096

// ---- scratch (allocation-free) ----
__device__ float g_h  [NTOK*Dq];
__device__ float g_q  [NTOK*Dq];
__device__ float g_k  [NTOK*Dq];
__device__ float g_v  [NTOK*Dq];
__device__ float g_att[NTOK*Dq];
__device__ float g_x2 [NTOK*Dq];
__device__ float g_h2 [NTOK*Dq];
__device__ float g_mlp[NTOK*Fq];

__device__ __forceinline__ uint32_t tf32r(float x) {
    uint32_t u;
    asm("cvt.rna.tf32.f32 %0, %1;" : "=r"(u) : "f"(x));
    return u;
}
__device__ __forceinline__ float tf32f(float x) {
    return __uint_as_float(tf32r(x));
}
__device__ __forceinline__ uint32_t tf32b(uint32_t xb) {
    uint32_t u;
    asm("cvt.rna.tf32.f32 %0, %1;" : "=r"(u) : "r"(xb));
    return u;
}
__device__ __forceinline__ uint32_t smem_u32(const void* p) {
    uint32_t a;
    asm("{ .reg .u64 t; cvta.to.shared.u64 t, %1; cvt.u32.u64 %0, t; }" : "=r"(a) : "l"(p));
    return a;
}
__device__ __forceinline__ void cp_async16(uint32_t dst, const void* src) {
    asm volatile("cp.async.ca.shared.global [%0], [%1], 16;" :: "r"(dst), "l"(src));
}
__device__ __forceinline__ void cp_commit() {
    asm volatile("cp.async.commit_group;" ::: "memory");
}
template <int N>
__device__ __forceinline__ void cp_wait() {
    asm volatile("cp.async.wait_group %0;" :: "n"(N) : "memory");
}
__device__ __forceinline__ void mma_tf32(float* c, const uint32_t* a, const uint32_t* b) {
    asm volatile(
        "mma.sync.aligned.m16n8k8.row.col.f32.tf32.tf32.f32 "
        "{%0,%1,%2,%3}, {%4,%5,%6,%7}, {%8,%9}, {%0,%1,%2,%3};"
        : "+f"(c[0]), "+f"(c[1]), "+f"(c[2]), "+f"(c[3])
        : "r"(a[0]), "r"(a[1]), "r"(a[2]), "r"(a[3]),
          "r"(b[0]), "r"(b[1]));
}

// ================= LayerNorm =================
__global__ void ln_kernel(const float* __restrict__ x,
                          const float* __restrict__ g,
                          const float* __restrict__ b,
                          float* __restrict__ out) {
    __shared__ float sm[32];
    int row = blockIdx.x;
    const float* xr = x + (size_t)row * Dq;
    float* outr = out + (size_t)row * Dq;
    float4 v4 = *(const float4*)(xr + threadIdx.x * 4);
    float sum = v4.x + v4.y + v4.z + v4.w;
    int lane = threadIdx.x & 31, wid = threadIdx.x >> 5;
#pragma unroll
    for (int o = 16; o > 0; o >>= 1) sum += __shfl_xor_sync(0xffffffffu, sum, o);
    if (lane == 0) sm[wid] = sum;
    __syncthreads();
    float s0 = (threadIdx.x < 8) ? sm[threadIdx.x] : 0.f;
    if (wid == 0) {
#pragma unroll
        for (int o = 4; o > 0; o >>= 1) s0 += __shfl_xor_sync(0xffffffffu, s0, o);
        if (lane == 0) sm[0] = s0;
    }
    __syncthreads();
    float mu = sm[0] * (1.0f / Dq);
    __syncthreads();
    float d0 = v4.x - mu, d1 = v4.y - mu, d2 = v4.z - mu, d3 = v4.w - mu;
    float vs = d0 * d0 + d1 * d1 + d2 * d2 + d3 * d3;
#pragma unroll
    for (int o = 16; o > 0; o >>= 1) vs += __shfl_xor_sync(0xffffffffu, vs, o);
    if (lane == 0) sm[wid] = vs;
    __syncthreads();
    float v0 = (threadIdx.x < 8) ? sm[threadIdx.x] : 0.f;
    if (wid == 0) {
#pragma unroll
        for (int o = 4; o > 0; o >>= 1) v0 += __shfl_xor_sync(0xffffffffu, v0, o);
        if (lane == 0) sm[0] = v0;
    }
    __syncthreads();
    float rstd = rsqrtf(sm[0] * (1.0f / Dq) + 1e-5f);
    int c = threadIdx.x * 4;
    float4 gg = *(const float4*)(g + c);
    float4 bb = *(const float4*)(b + c);
    float4 o;
    o.x = d0 * rstd * gg.x + bb.x;
    o.y = d1 * rstd * gg.y + bb.y;
    o.z = d2 * rstd * gg.z + bb.z;
    o.w = d3 * rstd * gg.w + bb.w;
    *(float4*)(outr + c) = o;
}

// ================= tf32 mma.sync GEMM (R5-proven 2-stage cp.async) =======
// EPI: 0 = bias, 1 = bias+gelu, 2 = bias+residual, 3 = bias+tf32-round
#define STRIDE 36
#define STAGE_FLOATS (2 * 128 * STRIDE)   // 9216 floats / stage
#define GEMM_SMEM (2 * STAGE_FLOATS * 4)  // 73728 B

template <int EPI>
__global__ void __launch_bounds__(256, 2)
gemm_mma(const float* __restrict__ A, const float* __restrict__ W,
         const float* __restrict__ bias, const float* __restrict__ res,
         float* __restrict__ C, int M, int N, int K) {
    extern __shared__ uint32_t smem[];
    const uint32_t smb = smem_u32(smem);
    const int tid = threadIdx.x;
    const int wid = tid >> 5, lane = tid & 31;
    const int warp_m = wid >> 2, warp_n = wid & 3;
    const int bm = blockIdx.y * 128, bn = blockIdx.x * 128;

    float acc[4][4][4];
#pragma unroll
    for (int i = 0; i < 4; i++)
#pragma unroll
        for (int j = 0; j < 4; j++)
#pragma unroll
            for (int u = 0; u < 4; u++) acc[i][j][u] = 0.f;

    const int lc = (tid & 7) * 4;
    const int aBase = (warp_m * 64 + (lane >> 2)) * STRIDE + (lane & 3);
    const int bBase = 128 * STRIDE + (warp_n * 32 + (lane >> 2)) * STRIDE + (lane & 3);
    const int nk = K >> 5;

    uint32_t dA[4], dW[4];
    const float* srcA[4];
    const float* srcW[4];
#pragma unroll
    for (int i = 0; i < 4; i++) {
        int idx = tid + i * 256;
        int r = idx >> 3;
        dA[i] = smb + (uint32_t)(r * STRIDE + lc) * 4u;
        dW[i] = smb + (uint32_t)((128 + r) * STRIDE + lc) * 4u;
        srcA[i] = A + (size_t)(bm + r) * K + lc;
        srcW[i] = W + (size_t)(bn + r) * K + lc;
    }

#pragma unroll
    for (int s = 0; s < 2; s++) {
        uint32_t so = (uint32_t)(s * STAGE_FLOATS * 4);
#pragma unroll
        for (int i = 0; i < 4; i++) {
            cp_async16(dA[i] + so, srcA[i] + s * 32);
            cp_async16(dW[i] + so, srcW[i] + s * 32);
        }
        cp_commit();
    }

    for (int kt = 0; kt < nk; kt++) {
        cp_wait<1>();
        __syncthreads();
        const uint32_t* st = smem + (kt & 1) * STAGE_FLOATS;
#pragma unroll
        for (int ks = 0; ks < 4; ks++) {
            uint32_t af[4][4], bf[4][2];
#pragma unroll
            for (int mt = 0; mt < 4; mt++) {
                const uint32_t* p = st + aBase + mt * (16 * STRIDE) + ks * 8;
                af[mt][0] = tf32b(p[0]);
                af[mt][1] = tf32b(p[8 * STRIDE]);
                af[mt][2] = tf32b(p[4]);
                af[mt][3] = tf32b(p[8 * STRIDE + 4]);
            }
#pragma unroll
            for (int nt = 0; nt < 4; nt++) {
                const uint32_t* p = st + bBase + nt * (8 * STRIDE) + ks * 8;
                bf[nt][0] = tf32b(p[0]);
                bf[nt][1] = tf32b(p[4]);
            }
#pragma unroll
            for (int mt = 0; mt < 4; mt++)
#pragma unroll
                for (int nt = 0; nt < 4; nt++)
                    mma_tf32(acc[mt][nt], af[mt], bf[nt]);
        }
        __syncthreads();
        if (kt + 2 < nk) {
            uint32_t so = (uint32_t)((kt & 1) * STAGE_FLOATS * 4);
            const int koff = (kt + 2) * 32;
#pragma unroll
            for (int i = 0; i < 4; i++) {
                cp_async16(dA[i] + so, srcA[i] + koff);
                cp_async16(dW[i] + so, srcW[i] + koff);
            }
        }
        cp_commit();
    }

#pragma unroll
    for (int mt = 0; mt < 4; mt++) {
#pragma unroll
        for (int nt = 0; nt < 4; nt++) {
            int row = bm + warp_m * 64 + mt * 16 + (lane >> 2);
            int col = bn + warp_n * 32 + nt * 8 + 2 * (lane & 3);
#pragma unroll
            for (int half = 0; half < 2; half++) {
                int r = row + half * 8;
                float v0 = acc[mt][nt][half * 2 + 0] + bias[col];
                float v1 = acc[mt][nt][half * 2 + 1] + bias[col + 1];
                if (EPI == 1) {
                    float z0 = 0.7978845608028654f * (v0 + 0.044715f * v0 * v0 * v0);
                    float z1 = 0.7978845608028654f * (v1 + 0.044715f * v1 * v1 * v1);
                    v0 = v0 / (1.f + __expf(-2.f * z0));
                    v1 = v1 / (1.f + __expf(-2.f * z1));
                }
                if (EPI == 2) {
                    v0 += res[(size_t)r * N + col];
                    v1 += res[(size_t)r * N + col + 1];
                }
                if (EPI == 3) {
                    v0 = tf32f(v0);
                    v1 = tf32f(v1);
                }
                float2 o; o.x = v0; o.y = v1;
                *(float2*)(C + (size_t)r * N + col) = o;
            }
        }
    }
}

// ================= tf32 mma flash attention (cp.async double-buffer) =====
// q,k,v pre-rounded tf32. 8 warps x 16 q-rows; KV tile 64 keys, 2 stages;
// softmax over 2 subtiles of 32 keys (register relief).
#define KSTR 68
#define VSTR 72
#define PSTR 36
#define ATT_SF (64*KSTR + 64*VSTR)                 // floats per stage: 8960
#define ATT_SMEM ((2*ATT_SF + 8*16*PSTR) * 4)      // 90112 B

__global__ void __launch_bounds__(256, 2)
attn_mma(const float* __restrict__ q, const float* __restrict__ k,
         const float* __restrict__ v, float* __restrict__ out) {
    extern __shared__ uint32_t sm[];
    const uint32_t smb = smem_u32(sm);
    uint32_t* Psm = sm + 2 * ATT_SF;
    const int tid = threadIdx.x, wid = tid >> 5, lane = tid & 31;
    const int g = lane >> 2, t = lane & 3;
    const int bh = blockIdx.x, b = bh >> 4, h = bh & 15;
    const int q0 = blockIdx.y * 128 + wid * 16;
    uint32_t* Pw = Psm + wid * 16 * PSTR;

    // staging coords: idx = tid + i*256 -> r = idx>>4 (0..63), c=(idx&15)*4
    const int sr = tid >> 4;            // base row (adds i*16)
    const int sc = (tid & 15) * 4;
    const float* kb0 = k + ((size_t)b * Sq) * Dq + h * HDq;
    const float* vb0 = v + ((size_t)b * Sq) * Dq + h * HDq;
    const uint32_t dK = smb + (uint32_t)(sr * KSTR + sc) * 4u;
    const uint32_t dV = smb + (uint32_t)(64 * KSTR + sr * VSTR + sc) * 4u;

    // Q fragments (pre-rounded; *0.125 exact)
    uint32_t aq[8][4];
    const float* qb = q + ((size_t)(b * Sq + q0)) * Dq + h * HDq;
#pragma unroll
    for (int ks = 0; ks < 8; ks++) {
        aq[ks][0] = __float_as_uint(qb[(size_t)g * Dq + ks * 8 + t] * 0.125f);
        aq[ks][1] = __float_as_uint(qb[(size_t)(g + 8) * Dq + ks * 8 + t] * 0.125f);
        aq[ks][2] = __float_as_uint(qb[(size_t)g * Dq + ks * 8 + t + 4] * 0.125f);
        aq[ks][3] = __float_as_uint(qb[(size_t)(g + 8) * Dq + ks * 8 + t + 4] * 0.125f);
    }
    float o[8][4];
#pragma unroll
    for (int nt = 0; nt < 8; nt++)
#pragma unroll
        for (int u = 0; u < 4; u++) o[nt][u] = 0.f;
    float m0 = -1e30f, m1 = -1e30f, l0 = 0.f, l1 = 0.f;

    const int NT = Sq / 64;
    // prologue: stage 0
    {
        const float* kb = kb0;
        const float* vb = vb0;
#pragma unroll
        for (int i = 0; i < 4; i++) {
            cp_async16(dK + 0, kb + (size_t)(sr + i * 16) * Dq + sc);
            cp_async16(dV + 0, vb + (size_t)(sr + i * 16) * Dq + sc);
        }
    }
    // NOTE: the above loop must offset dK/dV per i — rewritten below correctly.
    // (kept structure; real loads in loop below)

    for (int kt = 0; kt < NT; kt++) {
        if (kt == 0) {
            // issue stage 0 properly (replaces placeholder above; harmless dup writes)
            const float* kb = kb0;
            const float* vb = vb0;
#pragma unroll
            for (int i = 0; i < 4; i++) {
                cp_async16(dK + (uint32_t)(i * 16 * KSTR) * 4u, kb + (size_t)(sr + i * 16) * Dq + sc);
                cp_async16(dV + (uint32_t)(i * 16 * VSTR) * 4u, vb + (size_t)(sr + i * 16) * Dq + sc);
            }
            cp_commit();
        }
        cp_wait<0>();
        __syncthreads();
        if (kt + 1 < NT) {
            uint32_t so = (uint32_t)(((kt + 1) & 1) * ATT_SF * 4);
            const float* kb = kb0 + (size_t)(kt + 1) * 64 * Dq;
            const float* vb = vb0 + (size_t)(kt + 1) * 64 * Dq;
#pragma unroll
            for (int i = 0; i < 4; i++) {
                cp_async16(dK + so + (uint32_t)(i * 16 * KSTR) * 4u, kb + (size_t)(sr + i * 16) * Dq + sc);
                cp_async16(dV + so + (uint32_t)(i * 16 * VSTR) * 4u, vb + (size_t)(sr + i * 16) * Dq + sc);
            }
            cp_commit();
        }
        const uint32_t* Kst = sm + (kt & 1) * ATT_SF;
        const uint32_t* Vst = Kst + 64 * KSTR;

#pragma unroll
        for (int sub = 0; sub < 2; sub++) {
            float s[4][4];
#pragma unroll
            for (int nt = 0; nt < 4; nt++)
#pragma unroll
                for (int u = 0; u < 4; u++) s[nt][u] = 0.f;
#pragma unroll
            for (int ks = 0; ks < 8; ks++) {
#pragma unroll
                for (int nt = 0; nt < 4; nt++) {
                    uint32_t bf[2];
                    const uint32_t* p = Kst + (sub * 32 + nt * 8 + g) * KSTR + ks * 8 + t;
                    bf[0] = p[0];
                    bf[1] = p[4];
                    mma_tf32(s[nt], aq[ks], bf);
                }
            }
            // softmax update (32 keys)
            float mx0 = fmaxf(fmaxf(s[0][0], s[0][1]), fmaxf(s[1][0], s[1][1]));
            mx0 = fmaxf(mx0, fmaxf(fmaxf(s[2][0], s[2][1]), fmaxf(s[3][0], s[3][1])));
            float mx1 = fmaxf(fmaxf(s[0][2], s[0][3]), fmaxf(s[1][2], s[1][3]));
            mx1 = fmaxf(mx1, fmaxf(fmaxf(s[2][2], s[2][3]), fmaxf(s[3][2], s[3][3])));
            mx0 = fmaxf(mx0, __shfl_xor_sync(0xffffffffu, mx0, 1));
            mx0 = fmaxf(mx0, __shfl_xor_sync(0xffffffffu, mx0, 2));
            mx1 = fmaxf(mx1, __shfl_xor_sync(0xffffffffu, mx1, 1));
            mx1 = fmaxf(mx1, __shfl_xor_sync(0xffffffffu, mx1, 2));
            float nm0 = fmaxf(m0, mx0), nm1 = fmaxf(m1, mx1);
            float c0 = __expf(m0 - nm0), c1 = __expf(m1 - nm1);
            float sum0 = 0.f, sum1 = 0.f;
#pragma unroll
            for (int nt = 0; nt < 4; nt++) {
                s[nt][0] = __expf(s[nt][0] - nm0);
                s[nt][1] = __expf(s[nt][1] - nm0);
                s[nt][2] = __expf(s[nt][2] - nm1);
                s[nt][3] = __expf(s[nt][3] - nm1);
                sum0 += s[nt][0] + s[nt][1];
                sum1 += s[nt][2] + s[nt][3];
            }
            sum0 += __shfl_xor_sync(0xffffffffu, sum0, 1);
            sum0 += __shfl_xor_sync(0xffffffffu, sum0, 2);
            sum1 += __shfl_xor_sync(0xffffffffu, sum1, 1);
            sum1 += __shfl_xor_sync(0xffffffffu, sum1, 2);
            l0 = l0 * c0 + sum0;
            l1 = l1 * c1 + sum1;
#pragma unroll
            for (int nt = 0; nt < 8; nt++) {
                o[nt][0] *= c0; o[nt][1] *= c0;
                o[nt][2] *= c1; o[nt][3] *= c1;
            }
            m0 = nm0; m1 = nm1;

            // stage P subtile (16 rows x 32 keys), warp-private
#pragma unroll
            for (int nt = 0; nt < 4; nt++) {
                uint2 p0; p0.x = tf32r(s[nt][0]); p0.y = tf32r(s[nt][1]);
                *(uint2*)(Pw + g * PSTR + nt * 8 + 2 * t) = p0;
                uint2 p1; p1.x = tf32r(s[nt][2]); p1.y = tf32r(s[nt][3]);
                *(uint2*)(Pw + (g + 8) * PSTR + nt * 8 + 2 * t) = p1;
            }
            __syncwarp();

            // O += P V (32 keys)
#pragma unroll
            for (int ks = 0; ks < 4; ks++) {
                uint32_t ap[4];
                ap[0] = Pw[g * PSTR + ks * 8 + t];
                ap[1] = Pw[(g + 8) * PSTR + ks * 8 + t];
                ap[2] = Pw[g * PSTR + ks * 8 + t + 4];
                ap[3] = Pw[(g + 8) * PSTR + ks * 8 + t + 4];
#pragma unroll
                for (int nt = 0; nt < 8; nt++) {
                    uint32_t bf[2];
                    bf[0] = Vst[(sub * 32 + ks * 8 + t) * VSTR + nt * 8 + g];
                    bf[1] = Vst[(sub * 32 + ks * 8 + t + 4) * VSTR + nt * 8 + g];
                    mma_tf32(o[nt], ap, bf);
                }
            }
            __syncwarp();
        }
    }

    float i0 = 1.f / l0, i1 = 1.f / l1;
    float* ob = out + ((size_t)(b * Sq + q0)) * Dq + h * HDq;
#pragma unroll
    for (int nt = 0; nt < 8; nt++) {
        float2 w0; w0.x = o[nt][0] * i0; w0.y = o[nt][1] * i0;
        *(float2*)(ob + (size_t)g * Dq + nt * 8 + 2 * t) = w0;
        float2 w1; w1.x = o[nt][2] * i1; w1.y = o[nt][3] * i1;
        *(float2*)(ob + (size_t)(g + 8) * Dq + nt * 8 + 2 * t) = w1;
    }
}

// ================= launch =================
extern "C" void kernel_launch(void* const* d_in, const int* in_sizes, int n_in,
                              void* d_out, int out_size) {
    const float* x     = (const float*)d_in[0];
    const float* Wq    = (const float*)d_in[1];
    const float* bq    = (const float*)d_in[2];
    const float* Wk    = (const float*)d_in[3];
    const float* bk    = (const float*)d_in[4];
    const float* Wv    = (const float*)d_in[5];
    const float* bv    = (const float*)d_in[6];
    const float* Wo    = (const float*)d_in[7];
    const float* bo    = (const float*)d_in[8];
    const float* ln1_g = (const float*)d_in[9];
    const float* ln1_b = (const float*)d_in[10];
    const float* W1    = (const float*)d_in[11];
    const float* b1    = (const float*)d_in[12];
    const float* W2    = (const float*)d_in[13];
    const float* b2    = (const float*)d_in[14];
    const float* ln2_g = (const float*)d_in[15];
    const float* ln2_b = (const float*)d_in[16];
    float* out = (float*)d_out;

    float *h, *q, *k, *v, *att, *x2, *h2, *mlp;
    cudaGetSymbolAddress((void**)&h,   g_h);
    cudaGetSymbolAddress((void**)&q,   g_q);
    cudaGetSymbolAddress((void**)&k,   g_k);
    cudaGetSymbolAddress((void**)&v,   g_v);
    cudaGetSymbolAddress((void**)&att, g_att);
    cudaGetSymbolAddress((void**)&x2,  g_x2);
    cudaGetSymbolAddress((void**)&h2,  g_h2);
    cudaGetSymbolAddress((void**)&mlp, g_mlp);

    cudaFuncSetAttribute(gemm_mma<1>, cudaFuncAttributeMaxDynamicSharedMemorySize, GEMM_SMEM);
    cudaFuncSetAttribute(gemm_mma<2>, cudaFuncAttributeMaxDynamicSharedMemorySize, GEMM_SMEM);
    cudaFuncSetAttribute(gemm_mma<3>, cudaFuncAttributeMaxDynamicSharedMemorySize, GEMM_SMEM);
    cudaFuncSetAttribute(attn_mma, cudaFuncAttributeMaxDynamicSharedMemorySize, ATT_SMEM);

    ln_kernel<<<NTOK, 256>>>(x, ln1_g, ln1_b, h);

    dim3 gqkv(Dq / 128, NTOK / 128);
    gemm_mma<3><<<gqkv, 256, GEMM_SMEM>>>(h, Wq, bq, nullptr, q, NTOK, Dq, Dq);
    gemm_mma<3><<<gqkv, 256, GEMM_SMEM>>>(h, Wk, bk, nullptr, k, NTOK, Dq, Dq);
    gemm_mma<3><<<gqkv, 256, GEMM_SMEM>>>(h, Wv, bv, nullptr, v, NTOK, Dq, Dq);

    dim3 gattn(Bq * Hq, Sq / 128);
    attn_mma<<<gattn, 256, ATT_SMEM>>>(q, k, v, att);

    gemm_mma<2><<<gqkv, 256, GEMM_SMEM>>>(att, Wo, bo, x, x2, NTOK, Dq, Dq);

    ln_kernel<<<NTOK, 256>>>(x2, ln2_g, ln2_b, h2);

    dim3 g1(Fq / 128, NTOK / 128);
    gemm_mma<1><<<g1, 256, GEMM_SMEM>>>(h2, W1, b1, nullptr, mlp, NTOK, Fq, Dq);

    dim3 g2(Dq / 128, NTOK / 128);
    gemm_mma<2><<<g2, 256, GEMM_SMEM>>>(mlp, W2, b2, x2, out, NTOK, Dq, Fq);
}

// round 8
// speedup vs baseline: 1.1501x; 1.0354x over previous
#include <cuda_runtime.h>
#include <cstdint>
#include <math.h>

#define Bq 2
#define Sq 2048
#define Dq 1024
#define Hq 16
#define HDq 64
#define Fq 4096
#define NTOK (Bq*Sq)   // 4096

// ---- scratch (allocation-free) ----
__device__ float g_h  [NTOK*Dq];
__device__ float g_q  [NTOK*Dq];
__device__ float g_k  [NTOK*Dq];
__device__ float g_v  [NTOK*Dq];
__device__ float g_att[NTOK*Dq];
__device__ float g_x2 [NTOK*Dq];
__device__ float g_h2 [NTOK*Dq];
__device__ float g_mlp[NTOK*Fq];
// tf32-pre-rounded weights
__device__ float g_wq[Dq*Dq];
__device__ float g_wk[Dq*Dq];
__device__ float g_wv[Dq*Dq];
__device__ float g_wo[Dq*Dq];
__device__ float g_w1[Fq*Dq];
__device__ float g_w2[Dq*Fq];

__device__ __forceinline__ uint32_t tf32r(float x) {
    uint32_t u;
    asm("cvt.rna.tf32.f32 %0, %1;" : "=r"(u) : "f"(x));
    return u;
}
__device__ __forceinline__ float tf32f(float x) {
    return __uint_as_float(tf32r(x));
}
__device__ __forceinline__ uint32_t smem_u32(const void* p) {
    uint32_t a;
    asm("{ .reg .u64 t; cvta.to.shared.u64 t, %1; cvt.u32.u64 %0, t; }" : "=r"(a) : "l"(p));
    return a;
}
__device__ __forceinline__ void cp_async16(uint32_t dst, const void* src) {
    asm volatile("cp.async.ca.shared.global [%0], [%1], 16;" :: "r"(dst), "l"(src));
}
__device__ __forceinline__ void cp_commit() {
    asm volatile("cp.async.commit_group;" ::: "memory");
}
template <int N>
__device__ __forceinline__ void cp_wait() {
    asm volatile("cp.async.wait_group %0;" :: "n"(N) : "memory");
}
__device__ __forceinline__ void mma_tf32(float* c, const uint32_t* a, const uint32_t* b) {
    asm volatile(
        "mma.sync.aligned.m16n8k8.row.col.f32.tf32.tf32.f32 "
        "{%0,%1,%2,%3}, {%4,%5,%6,%7}, {%8,%9}, {%0,%1,%2,%3};"
        : "+f"(c[0]), "+f"(c[1]), "+f"(c[2]), "+f"(c[3])
        : "r"(a[0]), "r"(a[1]), "r"(a[2]), "r"(a[3]),
          "r"(b[0]), "r"(b[1]));
}

// ================= weight tf32 pre-round =================
__global__ void wcvt_kernel(const float* __restrict__ wq, const float* __restrict__ wk,
                            const float* __restrict__ wv, const float* __restrict__ wo,
                            const float* __restrict__ w1, const float* __restrict__ w2,
                            float* oq, float* ok, float* ov, float* oo,
                            float* o1, float* o2) {
    const int Qk = Dq * Dq / 4;
    int i4 = blockIdx.x * 256 + threadIdx.x;
    const float* s;
    float* d;
    int off;
    if (i4 < Qk)            { s = wq; d = oq; off = i4; }
    else if (i4 < 2 * Qk)   { s = wk; d = ok; off = i4 - Qk; }
    else if (i4 < 3 * Qk)   { s = wv; d = ov; off = i4 - 2 * Qk; }
    else if (i4 < 4 * Qk)   { s = wo; d = oo; off = i4 - 3 * Qk; }
    else if (i4 < 8 * Qk)   { s = w1; d = o1; off = i4 - 4 * Qk; }
    else                    { s = w2; d = o2; off = i4 - 8 * Qk; }
    float4 v = ((const float4*)s)[off];
    v.x = tf32f(v.x); v.y = tf32f(v.y); v.z = tf32f(v.z); v.w = tf32f(v.w);
    ((float4*)d)[off] = v;
}

// ================= LayerNorm (tf32-rounded output) =================
__global__ void ln_kernel(const float* __restrict__ x,
                          const float* __restrict__ g,
                          const float* __restrict__ b,
                          float* __restrict__ out) {
    __shared__ float sm[32];
    int row = blockIdx.x;
    const float* xr = x + (size_t)row * Dq;
    float* outr = out + (size_t)row * Dq;
    float4 v4 = *(const float4*)(xr + threadIdx.x * 4);
    float sum = v4.x + v4.y + v4.z + v4.w;
    int lane = threadIdx.x & 31, wid = threadIdx.x >> 5;
#pragma unroll
    for (int o = 16; o > 0; o >>= 1) sum += __shfl_xor_sync(0xffffffffu, sum, o);
    if (lane == 0) sm[wid] = sum;
    __syncthreads();
    float s0 = (threadIdx.x < 8) ? sm[threadIdx.x] : 0.f;
    if (wid == 0) {
#pragma unroll
        for (int o = 4; o > 0; o >>= 1) s0 += __shfl_xor_sync(0xffffffffu, s0, o);
        if (lane == 0) sm[0] = s0;
    }
    __syncthreads();
    float mu = sm[0] * (1.0f / Dq);
    __syncthreads();
    float d0 = v4.x - mu, d1 = v4.y - mu, d2 = v4.z - mu, d3 = v4.w - mu;
    float vs = d0 * d0 + d1 * d1 + d2 * d2 + d3 * d3;
#pragma unroll
    for (int o = 16; o > 0; o >>= 1) vs += __shfl_xor_sync(0xffffffffu, vs, o);
    if (lane == 0) sm[wid] = vs;
    __syncthreads();
    float v0 = (threadIdx.x < 8) ? sm[threadIdx.x] : 0.f;
    if (wid == 0) {
#pragma unroll
        for (int o = 4; o > 0; o >>= 1) v0 += __shfl_xor_sync(0xffffffffu, v0, o);
        if (lane == 0) sm[0] = v0;
    }
    __syncthreads();
    float rstd = rsqrtf(sm[0] * (1.0f / Dq) + 1e-5f);
    int c = threadIdx.x * 4;
    float4 gg = *(const float4*)(g + c);
    float4 bb = *(const float4*)(b + c);
    float4 o;
    o.x = tf32f(d0 * rstd * gg.x + bb.x);
    o.y = tf32f(d1 * rstd * gg.y + bb.y);
    o.z = tf32f(d2 * rstd * gg.z + bb.z);
    o.w = tf32f(d3 * rstd * gg.w + bb.w);
    *(float4*)(outr + c) = o;
}

// ================= tf32 mma.sync GEMM (2-stage cp.async, pre-rounded) =====
// EPI: 0 = bias, 1 = bias+gelu+round, 2 = bias+residual, 3 = bias+round
#define STRIDE 36
#define STAGE_FLOATS (2 * 128 * STRIDE)   // 9216 floats / stage
#define GEMM_SMEM (2 * STAGE_FLOATS * 4)  // 73728 B

template <int EPI>
__global__ void __launch_bounds__(256, 2)
gemm_mma(const float* __restrict__ A, const float* __restrict__ W,
         const float* __restrict__ bias, const float* __restrict__ res,
         float* __restrict__ C, int M, int N, int K) {
    extern __shared__ uint32_t smem[];
    const uint32_t smb = smem_u32(smem);
    const int tid = threadIdx.x;
    const int wid = tid >> 5, lane = tid & 31;
    const int warp_m = wid >> 2, warp_n = wid & 3;
    const int bm = blockIdx.y * 128, bn = blockIdx.x * 128;

    float acc[4][4][4];
#pragma unroll
    for (int i = 0; i < 4; i++)
#pragma unroll
        for (int j = 0; j < 4; j++)
#pragma unroll
            for (int u = 0; u < 4; u++) acc[i][j][u] = 0.f;

    const int lc = (tid & 7) * 4;
    const int aBase = (warp_m * 64 + (lane >> 2)) * STRIDE + (lane & 3);
    const int bBase = 128 * STRIDE + (warp_n * 32 + (lane >> 2)) * STRIDE + (lane & 3);
    const int nk = K >> 5;

    uint32_t dA[4], dW[4];
    const float* srcA[4];
    const float* srcW[4];
#pragma unroll
    for (int i = 0; i < 4; i++) {
        int idx = tid + i * 256;
        int r = idx >> 3;
        dA[i] = smb + (uint32_t)(r * STRIDE + lc) * 4u;
        dW[i] = smb + (uint32_t)((128 + r) * STRIDE + lc) * 4u;
        srcA[i] = A + (size_t)(bm + r) * K + lc;
        srcW[i] = W + (size_t)(bn + r) * K + lc;
    }

#pragma unroll
    for (int s = 0; s < 2; s++) {
        uint32_t so = (uint32_t)(s * STAGE_FLOATS * 4);
#pragma unroll
        for (int i = 0; i < 4; i++) {
            cp_async16(dA[i] + so, srcA[i] + s * 32);
            cp_async16(dW[i] + so, srcW[i] + s * 32);
        }
        cp_commit();
    }

    for (int kt = 0; kt < nk; kt++) {
        cp_wait<1>();
        __syncthreads();
        const uint32_t* st = smem + (kt & 1) * STAGE_FLOATS;
#pragma unroll
        for (int ks = 0; ks < 4; ks++) {
            uint32_t af[4][4], bf[4][2];
#pragma unroll
            for (int mt = 0; mt < 4; mt++) {
                const uint32_t* p = st + aBase + mt * (16 * STRIDE) + ks * 8;
                af[mt][0] = p[0];
                af[mt][1] = p[8 * STRIDE];
                af[mt][2] = p[4];
                af[mt][3] = p[8 * STRIDE + 4];
            }
#pragma unroll
            for (int nt = 0; nt < 4; nt++) {
                const uint32_t* p = st + bBase + nt * (8 * STRIDE) + ks * 8;
                bf[nt][0] = p[0];
                bf[nt][1] = p[4];
            }
#pragma unroll
            for (int mt = 0; mt < 4; mt++)
#pragma unroll
                for (int nt = 0; nt < 4; nt++)
                    mma_tf32(acc[mt][nt], af[mt], bf[nt]);
        }
        __syncthreads();
        if (kt + 2 < nk) {
            uint32_t so = (uint32_t)((kt & 1) * STAGE_FLOATS * 4);
            const int koff = (kt + 2) * 32;
#pragma unroll
            for (int i = 0; i < 4; i++) {
                cp_async16(dA[i] + so, srcA[i] + koff);
                cp_async16(dW[i] + so, srcW[i] + koff);
            }
        }
        cp_commit();
    }

#pragma unroll
    for (int mt = 0; mt < 4; mt++) {
#pragma unroll
        for (int nt = 0; nt < 4; nt++) {
            int row = bm + warp_m * 64 + mt * 16 + (lane >> 2);
            int col = bn + warp_n * 32 + nt * 8 + 2 * (lane & 3);
#pragma unroll
            for (int half = 0; half < 2; half++) {
                int r = row + half * 8;
                float v0 = acc[mt][nt][half * 2 + 0] + bias[col];
                float v1 = acc[mt][nt][half * 2 + 1] + bias[col + 1];
                if (EPI == 1) {
                    float z0 = 0.7978845608028654f * (v0 + 0.044715f * v0 * v0 * v0);
                    float z1 = 0.7978845608028654f * (v1 + 0.044715f * v1 * v1 * v1);
                    v0 = tf32f(v0 / (1.f + __expf(-2.f * z0)));
                    v1 = tf32f(v1 / (1.f + __expf(-2.f * z1)));
                }
                if (EPI == 2) {
                    v0 += res[(size_t)r * N + col];
                    v1 += res[(size_t)r * N + col + 1];
                }
                if (EPI == 3) {
                    v0 = tf32f(v0);
                    v1 = tf32f(v1);
                }
                float2 o; o.x = v0; o.y = v1;
                *(float2*)(C + (size_t)r * N + col) = o;
            }
        }
    }
}

// ================= tf32 mma flash attention (cp.async double-buffer) =====
// q,k,v pre-rounded tf32; output rounded (feeds Wo GEMM pre-rounded).
#define KSTR 68
#define VSTR 72
#define PSTR 36
#define ATT_SF (64*KSTR + 64*VSTR)
#define ATT_SMEM ((2*ATT_SF + 8*16*PSTR) * 4)

__global__ void __launch_bounds__(256, 2)
attn_mma(const float* __restrict__ q, const float* __restrict__ k,
         const float* __restrict__ v, float* __restrict__ out) {
    extern __shared__ uint32_t sm[];
    const uint32_t smb = smem_u32(sm);
    uint32_t* Psm = sm + 2 * ATT_SF;
    const int tid = threadIdx.x, wid = tid >> 5, lane = tid & 31;
    const int g = lane >> 2, t = lane & 3;
    const int bh = blockIdx.x, b = bh >> 4, h = bh & 15;
    const int q0 = blockIdx.y * 128 + wid * 16;
    uint32_t* Pw = Psm + wid * 16 * PSTR;

    const int sr = tid >> 4;
    const int sc = (tid & 15) * 4;
    const float* kb0 = k + ((size_t)b * Sq) * Dq + h * HDq;
    const float* vb0 = v + ((size_t)b * Sq) * Dq + h * HDq;
    const uint32_t dK = smb + (uint32_t)(sr * KSTR + sc) * 4u;
    const uint32_t dV = smb + (uint32_t)(64 * KSTR + sr * VSTR + sc) * 4u;

    uint32_t aq[8][4];
    const float* qb = q + ((size_t)(b * Sq + q0)) * Dq + h * HDq;
#pragma unroll
    for (int ks = 0; ks < 8; ks++) {
        aq[ks][0] = __float_as_uint(qb[(size_t)g * Dq + ks * 8 + t] * 0.125f);
        aq[ks][1] = __float_as_uint(qb[(size_t)(g + 8) * Dq + ks * 8 + t] * 0.125f);
        aq[ks][2] = __float_as_uint(qb[(size_t)g * Dq + ks * 8 + t + 4] * 0.125f);
        aq[ks][3] = __float_as_uint(qb[(size_t)(g + 8) * Dq + ks * 8 + t + 4] * 0.125f);
    }
    float o[8][4];
#pragma unroll
    for (int nt = 0; nt < 8; nt++)
#pragma unroll
        for (int u = 0; u < 4; u++) o[nt][u] = 0.f;
    float m0 = -1e30f, m1 = -1e30f, l0 = 0.f, l1 = 0.f;

    const int NT = Sq / 64;
    // prologue: stage 0 (correct per-row offsets; no duplicate-address writes)
#pragma unroll
    for (int i = 0; i < 4; i++) {
        cp_async16(dK + (uint32_t)(i * 16 * KSTR) * 4u, kb0 + (size_t)(sr + i * 16) * Dq + sc);
        cp_async16(dV + (uint32_t)(i * 16 * VSTR) * 4u, vb0 + (size_t)(sr + i * 16) * Dq + sc);
    }
    cp_commit();

    for (int kt = 0; kt < NT; kt++) {
        cp_wait<0>();
        __syncthreads();
        if (kt + 1 < NT) {
            uint32_t so = (uint32_t)(((kt + 1) & 1) * ATT_SF * 4);
            const float* kb = kb0 + (size_t)(kt + 1) * 64 * Dq;
            const float* vb = vb0 + (size_t)(kt + 1) * 64 * Dq;
#pragma unroll
            for (int i = 0; i < 4; i++) {
                cp_async16(dK + so + (uint32_t)(i * 16 * KSTR) * 4u, kb + (size_t)(sr + i * 16) * Dq + sc);
                cp_async16(dV + so + (uint32_t)(i * 16 * VSTR) * 4u, vb + (size_t)(sr + i * 16) * Dq + sc);
            }
            cp_commit();
        }
        const uint32_t* Kst = sm + (kt & 1) * ATT_SF;
        const uint32_t* Vst = Kst + 64 * KSTR;

#pragma unroll
        for (int sub = 0; sub < 2; sub++) {
            float s[4][4];
#pragma unroll
            for (int nt = 0; nt < 4; nt++)
#pragma unroll
                for (int u = 0; u < 4; u++) s[nt][u] = 0.f;
#pragma unroll
            for (int ks = 0; ks < 8; ks++) {
#pragma unroll
                for (int nt = 0; nt < 4; nt++) {
                    uint32_t bf[2];
                    const uint32_t* p = Kst + (sub * 32 + nt * 8 + g) * KSTR + ks * 8 + t;
                    bf[0] = p[0];
                    bf[1] = p[4];
                    mma_tf32(s[nt], aq[ks], bf);
                }
            }
            float mx0 = fmaxf(fmaxf(s[0][0], s[0][1]), fmaxf(s[1][0], s[1][1]));
            mx0 = fmaxf(mx0, fmaxf(fmaxf(s[2][0], s[2][1]), fmaxf(s[3][0], s[3][1])));
            float mx1 = fmaxf(fmaxf(s[0][2], s[0][3]), fmaxf(s[1][2], s[1][3]));
            mx1 = fmaxf(mx1, fmaxf(fmaxf(s[2][2], s[2][3]), fmaxf(s[3][2], s[3][3])));
            mx0 = fmaxf(mx0, __shfl_xor_sync(0xffffffffu, mx0, 1));
            mx0 = fmaxf(mx0, __shfl_xor_sync(0xffffffffu, mx0, 2));
            mx1 = fmaxf(mx1, __shfl_xor_sync(0xffffffffu, mx1, 1));
            mx1 = fmaxf(mx1, __shfl_xor_sync(0xffffffffu, mx1, 2));
            float nm0 = fmaxf(m0, mx0), nm1 = fmaxf(m1, mx1);
            float c0 = __expf(m0 - nm0), c1 = __expf(m1 - nm1);
            float sum0 = 0.f, sum1 = 0.f;
#pragma unroll
            for (int nt = 0; nt < 4; nt++) {
                s[nt][0] = __expf(s[nt][0] - nm0);
                s[nt][1] = __expf(s[nt][1] - nm0);
                s[nt][2] = __expf(s[nt][2] - nm1);
                s[nt][3] = __expf(s[nt][3] - nm1);
                sum0 += s[nt][0] + s[nt][1];
                sum1 += s[nt][2] + s[nt][3];
            }
            sum0 += __shfl_xor_sync(0xffffffffu, sum0, 1);
            sum0 += __shfl_xor_sync(0xffffffffu, sum0, 2);
            sum1 += __shfl_xor_sync(0xffffffffu, sum1, 1);
            sum1 += __shfl_xor_sync(0xffffffffu, sum1, 2);
            l0 = l0 * c0 + sum0;
            l1 = l1 * c1 + sum1;
#pragma unroll
            for (int nt = 0; nt < 8; nt++) {
                o[nt][0] *= c0; o[nt][1] *= c0;
                o[nt][2] *= c1; o[nt][3] *= c1;
            }
            m0 = nm0; m1 = nm1;

#pragma unroll
            for (int nt = 0; nt < 4; nt++) {
                uint2 p0; p0.x = tf32r(s[nt][0]); p0.y = tf32r(s[nt][1]);
                *(uint2*)(Pw + g * PSTR + nt * 8 + 2 * t) = p0;
                uint2 p1; p1.x = tf32r(s[nt][2]); p1.y = tf32r(s[nt][3]);
                *(uint2*)(Pw + (g + 8) * PSTR + nt * 8 + 2 * t) = p1;
            }
            __syncwarp();

#pragma unroll
            for (int ks = 0; ks < 4; ks++) {
                uint32_t ap[4];
                ap[0] = Pw[g * PSTR + ks * 8 + t];
                ap[1] = Pw[(g + 8) * PSTR + ks * 8 + t];
                ap[2] = Pw[g * PSTR + ks * 8 + t + 4];
                ap[3] = Pw[(g + 8) * PSTR + ks * 8 + t + 4];
#pragma unroll
                for (int nt = 0; nt < 8; nt++) {
                    uint32_t bf[2];
                    bf[0] = Vst[(sub * 32 + ks * 8 + t) * VSTR + nt * 8 + g];
                    bf[1] = Vst[(sub * 32 + ks * 8 + t + 4) * VSTR + nt * 8 + g];
                    mma_tf32(o[nt], ap, bf);
                }
            }
            __syncwarp();
        }
    }

    float i0 = 1.f / l0, i1 = 1.f / l1;
    float* ob = out + ((size_t)(b * Sq + q0)) * Dq + h * HDq;
#pragma unroll
    for (int nt = 0; nt < 8; nt++) {
        float2 w0; w0.x = tf32f(o[nt][0] * i0); w0.y = tf32f(o[nt][1] * i0);
        *(float2*)(ob + (size_t)g * Dq + nt * 8 + 2 * t) = w0;
        float2 w1; w1.x = tf32f(o[nt][2] * i1); w1.y = tf32f(o[nt][3] * i1);
        *(float2*)(ob + (size_t)(g + 8) * Dq + nt * 8 + 2 * t) = w1;
    }
}

// ================= launch =================
extern "C" void kernel_launch(void* const* d_in, const int* in_sizes, int n_in,
                              void* d_out, int out_size) {
    const float* x     = (const float*)d_in[0];
    const float* Wq    = (const float*)d_in[1];
    const float* bq    = (const float*)d_in[2];
    const float* Wk    = (const float*)d_in[3];
    const float* bk    = (const float*)d_in[4];
    const float* Wv    = (const float*)d_in[5];
    const float* bv    = (const float*)d_in[6];
    const float* Wo    = (const float*)d_in[7];
    const float* bo    = (const float*)d_in[8];
    const float* ln1_g = (const float*)d_in[9];
    const float* ln1_b = (const float*)d_in[10];
    const float* W1    = (const float*)d_in[11];
    const float* b1    = (const float*)d_in[12];
    const float* W2    = (const float*)d_in[13];
    const float* b2    = (const float*)d_in[14];
    const float* ln2_g = (const float*)d_in[15];
    const float* ln2_b = (const float*)d_in[16];
    float* out = (float*)d_out;

    float *h, *q, *k, *v, *att, *x2, *h2, *mlp;
    float *wq, *wk, *wv, *wo, *w1, *w2;
    cudaGetSymbolAddress((void**)&h,   g_h);
    cudaGetSymbolAddress((void**)&q,   g_q);
    cudaGetSymbolAddress((void**)&k,   g_k);
    cudaGetSymbolAddress((void**)&v,   g_v);
    cudaGetSymbolAddress((void**)&att, g_att);
    cudaGetSymbolAddress((void**)&x2,  g_x2);
    cudaGetSymbolAddress((void**)&h2,  g_h2);
    cudaGetSymbolAddress((void**)&mlp, g_mlp);
    cudaGetSymbolAddress((void**)&wq,  g_wq);
    cudaGetSymbolAddress((void**)&wk,  g_wk);
    cudaGetSymbolAddress((void**)&wv,  g_wv);
    cudaGetSymbolAddress((void**)&wo,  g_wo);
    cudaGetSymbolAddress((void**)&w1,  g_w1);
    cudaGetSymbolAddress((void**)&w2,  g_w2);

    cudaFuncSetAttribute(gemm_mma<1>, cudaFuncAttributeMaxDynamicSharedMemorySize, GEMM_SMEM);
    cudaFuncSetAttribute(gemm_mma<2>, cudaFuncAttributeMaxDynamicSharedMemorySize, GEMM_SMEM);
    cudaFuncSetAttribute(gemm_mma<3>, cudaFuncAttributeMaxDynamicSharedMemorySize, GEMM_SMEM);
    cudaFuncSetAttribute(attn_mma, cudaFuncAttributeMaxDynamicSharedMemorySize, ATT_SMEM);

    // 0) pre-round weights (once per call; deterministic)
    const int WTOT4 = (4 * Dq * Dq + 2 * Fq * Dq) / 4;
    wcvt_kernel<<<WTOT4 / 256, 256>>>(Wq, Wk, Wv, Wo, W1, W2, wq, wk, wv, wo, w1, w2);

    // 1) LN1 (rounded)
    ln_kernel<<<NTOK, 256>>>(x, ln1_g, ln1_b, h);

    // 2) QKV (rounded outputs)
    dim3 gqkv(Dq / 128, NTOK / 128);
    gemm_mma<3><<<gqkv, 256, GEMM_SMEM>>>(h, wq, bq, nullptr, q, NTOK, Dq, Dq);
    gemm_mma<3><<<gqkv, 256, GEMM_SMEM>>>(h, wk, bk, nullptr, k, NTOK, Dq, Dq);
    gemm_mma<3><<<gqkv, 256, GEMM_SMEM>>>(h, wv, bv, nullptr, v, NTOK, Dq, Dq);

    // 3) attention (rounded output)
    dim3 gattn(Bq * Hq, Sq / 128);
    attn_mma<<<gattn, 256, ATT_SMEM>>>(q, k, v, att);

    // 4) output projection + residual
    gemm_mma<2><<<gqkv, 256, GEMM_SMEM>>>(att, wo, bo, x, x2, NTOK, Dq, Dq);

    // 5) LN2 (rounded)
    ln_kernel<<<NTOK, 256>>>(x2, ln2_g, ln2_b, h2);

    // 6) MLP up + gelu (rounded)
    dim3 g1(Fq / 128, NTOK / 128);
    gemm_mma<1><<<g1, 256, GEMM_SMEM>>>(h2, w1, b1, nullptr, mlp, NTOK, Fq, Dq);

    // 7) MLP down + residual -> out
    dim3 g2(Dq / 128, NTOK / 128);
    gemm_mma<2><<<g2, 256, GEMM_SMEM>>>(mlp, w2, b2, x2, out, NTOK, Dq, Fq);
}

// round 9
// speedup vs baseline: 1.5856x; 1.3787x over previous
#include <cuda_runtime.h>
#include <cuda_fp16.h>
#include <cstdint>
#include <math.h>

#define Bq 2
#define Sq 2048
#define Dq 1024
#define Hq 16
#define HDq 64
#define Fq 4096
#define NTOK (Bq*Sq)   // 4096

// ---- scratch (allocation-free) ----
__device__ __half g_h  [NTOK*Dq];
__device__ float  g_q  [NTOK*Dq];
__device__ float  g_k  [NTOK*Dq];
__device__ float  g_v  [NTOK*Dq];
__device__ __half g_att[NTOK*Dq];
__device__ float  g_x2 [NTOK*Dq];
__device__ __half g_h2 [NTOK*Dq];
__device__ __half g_mlp[NTOK*Fq];
// fp16 weights
__device__ __half g_wq[Dq*Dq];
__device__ __half g_wk[Dq*Dq];
__device__ __half g_wv[Dq*Dq];
__device__ __half g_wo[Dq*Dq];
__device__ __half g_w1[Fq*Dq];
__device__ __half g_w2[Dq*Fq];

__device__ __forceinline__ uint32_t tf32r(float x) {
    uint32_t u;
    asm("cvt.rna.tf32.f32 %0, %1;" : "=r"(u) : "f"(x));
    return u;
}
__device__ __forceinline__ float tf32f(float x) {
    return __uint_as_float(tf32r(x));
}
__device__ __forceinline__ uint32_t smem_u32(const void* p) {
    uint32_t a;
    asm("{ .reg .u64 t; cvta.to.shared.u64 t, %1; cvt.u32.u64 %0, t; }" : "=r"(a) : "l"(p));
    return a;
}
__device__ __forceinline__ void cp_async16(uint32_t dst, const void* src) {
    asm volatile("cp.async.ca.shared.global [%0], [%1], 16;" :: "r"(dst), "l"(src));
}
__device__ __forceinline__ void cp_commit() {
    asm volatile("cp.async.commit_group;" ::: "memory");
}
template <int N>
__device__ __forceinline__ void cp_wait() {
    asm volatile("cp.async.wait_group %0;" :: "n"(N) : "memory");
}
// tf32 m16n8k8 (attention)
__device__ __forceinline__ void mma_tf32(float* c, const uint32_t* a, const uint32_t* b) {
    asm volatile(
        "mma.sync.aligned.m16n8k8.row.col.f32.tf32.tf32.f32 "
        "{%0,%1,%2,%3}, {%4,%5,%6,%7}, {%8,%9}, {%0,%1,%2,%3};"
        : "+f"(c[0]), "+f"(c[1]), "+f"(c[2]), "+f"(c[3])
        : "r"(a[0]), "r"(a[1]), "r"(a[2]), "r"(a[3]),
          "r"(b[0]), "r"(b[1]));
}
// fp16 m16n8k16, f32 accumulate (GEMMs)
__device__ __forceinline__ void mma_f16(float* c, const uint32_t* a, const uint32_t* b) {
    asm volatile(
        "mma.sync.aligned.m16n8k16.row.col.f32.f16.f16.f32 "
        "{%0,%1,%2,%3}, {%4,%5,%6,%7}, {%8,%9}, {%0,%1,%2,%3};"
        : "+f"(c[0]), "+f"(c[1]), "+f"(c[2]), "+f"(c[3])
        : "r"(a[0]), "r"(a[1]), "r"(a[2]), "r"(a[3]),
          "r"(b[0]), "r"(b[1]));
}

// ================= weight fp16 convert =================
__global__ void wcvt_kernel(const float* __restrict__ wq, const float* __restrict__ wk,
                            const float* __restrict__ wv, const float* __restrict__ wo,
                            const float* __restrict__ w1, const float* __restrict__ w2,
                            __half* oq, __half* ok, __half* ov, __half* oo,
                            __half* o1, __half* o2) {
    const int Qk = Dq * Dq / 4;
    int i4 = blockIdx.x * 256 + threadIdx.x;
    const float* s;
    __half* d;
    int off;
    if (i4 < Qk)            { s = wq; d = oq; off = i4; }
    else if (i4 < 2 * Qk)   { s = wk; d = ok; off = i4 - Qk; }
    else if (i4 < 3 * Qk)   { s = wv; d = ov; off = i4 - 2 * Qk; }
    else if (i4 < 4 * Qk)   { s = wo; d = oo; off = i4 - 3 * Qk; }
    else if (i4 < 8 * Qk)   { s = w1; d = o1; off = i4 - 4 * Qk; }
    else                    { s = w2; d = o2; off = i4 - 8 * Qk; }
    float4 v = ((const float4*)s)[off];
    __half2 lo = __floats2half2_rn(v.x, v.y);
    __half2 hi = __floats2half2_rn(v.z, v.w);
    __half2* dp = (__half2*)(d + (size_t)off * 4);
    dp[0] = lo; dp[1] = hi;
}

// ================= LayerNorm (fp16 output) =================
__global__ void ln_kernel(const float* __restrict__ x,
                          const float* __restrict__ g,
                          const float* __restrict__ b,
                          __half* __restrict__ out) {
    __shared__ float sm[32];
    int row = blockIdx.x;
    const float* xr = x + (size_t)row * Dq;
    __half* outr = out + (size_t)row * Dq;
    float4 v4 = *(const float4*)(xr + threadIdx.x * 4);
    float sum = v4.x + v4.y + v4.z + v4.w;
    int lane = threadIdx.x & 31, wid = threadIdx.x >> 5;
#pragma unroll
    for (int o = 16; o > 0; o >>= 1) sum += __shfl_xor_sync(0xffffffffu, sum, o);
    if (lane == 0) sm[wid] = sum;
    __syncthreads();
    float s0 = (threadIdx.x < 8) ? sm[threadIdx.x] : 0.f;
    if (wid == 0) {
#pragma unroll
        for (int o = 4; o > 0; o >>= 1) s0 += __shfl_xor_sync(0xffffffffu, s0, o);
        if (lane == 0) sm[0] = s0;
    }
    __syncthreads();
    float mu = sm[0] * (1.0f / Dq);
    __syncthreads();
    float d0 = v4.x - mu, d1 = v4.y - mu, d2 = v4.z - mu, d3 = v4.w - mu;
    float vs = d0 * d0 + d1 * d1 + d2 * d2 + d3 * d3;
#pragma unroll
    for (int o = 16; o > 0; o >>= 1) vs += __shfl_xor_sync(0xffffffffu, vs, o);
    if (lane == 0) sm[wid] = vs;
    __syncthreads();
    float v0 = (threadIdx.x < 8) ? sm[threadIdx.x] : 0.f;
    if (wid == 0) {
#pragma unroll
        for (int o = 4; o > 0; o >>= 1) v0 += __shfl_xor_sync(0xffffffffu, v0, o);
        if (lane == 0) sm[0] = v0;
    }
    __syncthreads();
    float rstd = rsqrtf(sm[0] * (1.0f / Dq) + 1e-5f);
    int c = threadIdx.x * 4;
    float4 gg = *(const float4*)(g + c);
    float4 bb = *(const float4*)(b + c);
    __half2* op = (__half2*)(outr + c);
    op[0] = __floats2half2_rn(d0 * rstd * gg.x + bb.x, d1 * rstd * gg.y + bb.y);
    op[1] = __floats2half2_rn(d2 * rstd * gg.z + bb.z, d3 * rstd * gg.w + bb.w);
}

// ================= fp16 mma.sync GEMM (2-stage cp.async) =================
// C[M,N] = A[M,K] @ W[N,K]^T + bias. Tile 128x128, K-chunk 32 halves.
// 8 warps 2x4, warp tile 64x32; 2 m16n8k16 k-steps per chunk.
// smem rows padded to 40 halves (80 B) - conflict-free for cp.async & frags.
// EPI: 0 = bias + tf32-round -> float out (QKV)
//      1 = bias + gelu -> half out (mlp)
//      2 = bias + residual -> float out (Wo, W2)
#define HSTR 40
#define STAGE_HALVES (2 * 128 * HSTR)       // 10240 halves
#define STAGE_BYTES  (STAGE_HALVES * 2)     // 20480 B
#define GEMM_SMEM    (2 * STAGE_BYTES)      // 40960 B

template <int EPI>
__global__ void __launch_bounds__(256, 2)
gemm_mma(const __half* __restrict__ A, const __half* __restrict__ W,
         const float* __restrict__ bias, const float* __restrict__ res,
         void* __restrict__ Cv, int M, int N, int K) {
    extern __shared__ __half smem[];
    const uint32_t smb = smem_u32(smem);
    const int tid = threadIdx.x;
    const int wid = tid >> 5, lane = tid & 31;
    const int warp_m = wid >> 2, warp_n = wid & 3;
    const int g = lane >> 2, t = lane & 3;
    const int bm = blockIdx.y * 128, bn = blockIdx.x * 128;

    float acc[4][4][4];
#pragma unroll
    for (int i = 0; i < 4; i++)
#pragma unroll
        for (int j = 0; j < 4; j++)
#pragma unroll
            for (int u = 0; u < 4; u++) acc[i][j][u] = 0.f;

    // cp.async map: idx = tid + i*256 (i=0,1): row = idx>>2, seg = idx&3 (16B)
    const int r0 = tid >> 2, r1 = (tid + 256) >> 2;
    const int sg = (tid & 3) * 8;            // half offset within row
    uint32_t dA[2], dW[2];
    const __half* srcA[2];
    const __half* srcW[2];
    dA[0] = smb + (uint32_t)(r0 * 80 + sg * 2);
    dA[1] = smb + (uint32_t)(r1 * 80 + sg * 2);
    dW[0] = dA[0] + 10240u;   // W region at halves offset 128*40
    dW[1] = dA[1] + 10240u;
    srcA[0] = A + (size_t)(bm + r0) * K + sg;
    srcA[1] = A + (size_t)(bm + r1) * K + sg;
    srcW[0] = W + (size_t)(bn + r0) * K + sg;
    srcW[1] = W + (size_t)(bn + r1) * K + sg;

    // fragment bases (half offsets)
    const int aBase = (warp_m * 64 + g) * HSTR + 2 * t;
    const int bBase = 128 * HSTR + (warp_n * 32 + g) * HSTR + 2 * t;
    const int nk = K >> 5;

#pragma unroll
    for (int s = 0; s < 2; s++) {
        uint32_t so = (uint32_t)(s * STAGE_BYTES);
#pragma unroll
        for (int i = 0; i < 2; i++) {
            cp_async16(dA[i] + so, srcA[i] + s * 32);
            cp_async16(dW[i] + so, srcW[i] + s * 32);
        }
        cp_commit();
    }

    for (int kt = 0; kt < nk; kt++) {
        cp_wait<1>();
        __syncthreads();
        const __half* st = smem + (size_t)(kt & 1) * STAGE_HALVES;
#pragma unroll
        for (int ks = 0; ks < 2; ks++) {
            uint32_t af[4][4], bf[4][2];
#pragma unroll
            for (int mt = 0; mt < 4; mt++) {
                const __half* p = st + aBase + mt * (16 * HSTR) + ks * 16;
                af[mt][0] = *(const uint32_t*)(p);
                af[mt][1] = *(const uint32_t*)(p + 8 * HSTR);
                af[mt][2] = *(const uint32_t*)(p + 8);
                af[mt][3] = *(const uint32_t*)(p + 8 * HSTR + 8);
            }
#pragma unroll
            for (int nt = 0; nt < 4; nt++) {
                const __half* p = st + bBase + nt * (8 * HSTR) + ks * 16;
                bf[nt][0] = *(const uint32_t*)(p);
                bf[nt][1] = *(const uint32_t*)(p + 8);
            }
#pragma unroll
            for (int mt = 0; mt < 4; mt++)
#pragma unroll
                for (int nt = 0; nt < 4; nt++)
                    mma_f16(acc[mt][nt], af[mt], bf[nt]);
        }
        __syncthreads();
        if (kt + 2 < nk) {
            uint32_t so = (uint32_t)((kt & 1) * STAGE_BYTES);
            const int koff = (kt + 2) * 32;
#pragma unroll
            for (int i = 0; i < 2; i++) {
                cp_async16(dA[i] + so, srcA[i] + koff);
                cp_async16(dW[i] + so, srcW[i] + koff);
            }
        }
        cp_commit();
    }

    // epilogue
#pragma unroll
    for (int mt = 0; mt < 4; mt++) {
#pragma unroll
        for (int nt = 0; nt < 4; nt++) {
            int row = bm + warp_m * 64 + mt * 16 + g;
            int col = bn + warp_n * 32 + nt * 8 + 2 * t;
#pragma unroll
            for (int half_i = 0; half_i < 2; half_i++) {
                int r = row + half_i * 8;
                float v0 = acc[mt][nt][half_i * 2 + 0] + bias[col];
                float v1 = acc[mt][nt][half_i * 2 + 1] + bias[col + 1];
                if (EPI == 0) {
                    float2 o; o.x = tf32f(v0); o.y = tf32f(v1);
                    *(float2*)((float*)Cv + (size_t)r * N + col) = o;
                } else if (EPI == 1) {
                    float z0 = 0.7978845608028654f * (v0 + 0.044715f * v0 * v0 * v0);
                    float z1 = 0.7978845608028654f * (v1 + 0.044715f * v1 * v1 * v1);
                    v0 = v0 / (1.f + __expf(-2.f * z0));
                    v1 = v1 / (1.f + __expf(-2.f * z1));
                    *(__half2*)((__half*)Cv + (size_t)r * N + col) = __floats2half2_rn(v0, v1);
                } else {
                    v0 += res[(size_t)r * N + col];
                    v1 += res[(size_t)r * N + col + 1];
                    float2 o; o.x = v0; o.y = v1;
                    *(float2*)((float*)Cv + (size_t)r * N + col) = o;
                }
            }
        }
    }
}

// ================= tf32 mma flash attention (cp.async double-buffer) =====
// q,k,v tf32-rounded float; output fp16 (feeds Wo GEMM).
#define KSTR 68
#define VSTR 72
#define PSTR 36
#define ATT_SF (64*KSTR + 64*VSTR)
#define ATT_SMEM ((2*ATT_SF + 8*16*PSTR) * 4)

__global__ void __launch_bounds__(256, 2)
attn_mma(const float* __restrict__ q, const float* __restrict__ k,
         const float* __restrict__ v, __half* __restrict__ out) {
    extern __shared__ uint32_t sm[];
    const uint32_t smb = smem_u32(sm);
    uint32_t* Psm = sm + 2 * ATT_SF;
    const int tid = threadIdx.x, wid = tid >> 5, lane = tid & 31;
    const int g = lane >> 2, t = lane & 3;
    const int bh = blockIdx.x, b = bh >> 4, h = bh & 15;
    const int q0 = blockIdx.y * 128 + wid * 16;
    uint32_t* Pw = Psm + wid * 16 * PSTR;

    const int sr = tid >> 4;
    const int sc = (tid & 15) * 4;
    const float* kb0 = k + ((size_t)b * Sq) * Dq + h * HDq;
    const float* vb0 = v + ((size_t)b * Sq) * Dq + h * HDq;
    const uint32_t dK = smb + (uint32_t)(sr * KSTR + sc) * 4u;
    const uint32_t dV = smb + (uint32_t)(64 * KSTR + sr * VSTR + sc) * 4u;

    uint32_t aq[8][4];
    const float* qb = q + ((size_t)(b * Sq + q0)) * Dq + h * HDq;
#pragma unroll
    for (int ks = 0; ks < 8; ks++) {
        aq[ks][0] = __float_as_uint(qb[(size_t)g * Dq + ks * 8 + t] * 0.125f);
        aq[ks][1] = __float_as_uint(qb[(size_t)(g + 8) * Dq + ks * 8 + t] * 0.125f);
        aq[ks][2] = __float_as_uint(qb[(size_t)g * Dq + ks * 8 + t + 4] * 0.125f);
        aq[ks][3] = __float_as_uint(qb[(size_t)(g + 8) * Dq + ks * 8 + t + 4] * 0.125f);
    }
    float o[8][4];
#pragma unroll
    for (int nt = 0; nt < 8; nt++)
#pragma unroll
        for (int u = 0; u < 4; u++) o[nt][u] = 0.f;
    float m0 = -1e30f, m1 = -1e30f, l0 = 0.f, l1 = 0.f;

    const int NT = Sq / 64;
#pragma unroll
    for (int i = 0; i < 4; i++) {
        cp_async16(dK + (uint32_t)(i * 16 * KSTR) * 4u, kb0 + (size_t)(sr + i * 16) * Dq + sc);
        cp_async16(dV + (uint32_t)(i * 16 * VSTR) * 4u, vb0 + (size_t)(sr + i * 16) * Dq + sc);
    }
    cp_commit();

    for (int kt = 0; kt < NT; kt++) {
        cp_wait<0>();
        __syncthreads();
        if (kt + 1 < NT) {
            uint32_t so = (uint32_t)(((kt + 1) & 1) * ATT_SF * 4);
            const float* kb = kb0 + (size_t)(kt + 1) * 64 * Dq;
            const float* vb = vb0 + (size_t)(kt + 1) * 64 * Dq;
#pragma unroll
            for (int i = 0; i < 4; i++) {
                cp_async16(dK + so + (uint32_t)(i * 16 * KSTR) * 4u, kb + (size_t)(sr + i * 16) * Dq + sc);
                cp_async16(dV + so + (uint32_t)(i * 16 * VSTR) * 4u, vb + (size_t)(sr + i * 16) * Dq + sc);
            }
            cp_commit();
        }
        const uint32_t* Kst = sm + (kt & 1) * ATT_SF;
        const uint32_t* Vst = Kst + 64 * KSTR;

#pragma unroll
        for (int sub = 0; sub < 2; sub++) {
            float s[4][4];
#pragma unroll
            for (int nt = 0; nt < 4; nt++)
#pragma unroll
                for (int u = 0; u < 4; u++) s[nt][u] = 0.f;
#pragma unroll
            for (int ks = 0; ks < 8; ks++) {
#pragma unroll
                for (int nt = 0; nt < 4; nt++) {
                    uint32_t bf[2];
                    const uint32_t* p = Kst + (sub * 32 + nt * 8 + g) * KSTR + ks * 8 + t;
                    bf[0] = p[0];
                    bf[1] = p[4];
                    mma_tf32(s[nt], aq[ks], bf);
                }
            }
            float mx0 = fmaxf(fmaxf(s[0][0], s[0][1]), fmaxf(s[1][0], s[1][1]));
            mx0 = fmaxf(mx0, fmaxf(fmaxf(s[2][0], s[2][1]), fmaxf(s[3][0], s[3][1])));
            float mx1 = fmaxf(fmaxf(s[0][2], s[0][3]), fmaxf(s[1][2], s[1][3]));
            mx1 = fmaxf(mx1, fmaxf(fmaxf(s[2][2], s[2][3]), fmaxf(s[3][2], s[3][3])));
            mx0 = fmaxf(mx0, __shfl_xor_sync(0xffffffffu, mx0, 1));
            mx0 = fmaxf(mx0, __shfl_xor_sync(0xffffffffu, mx0, 2));
            mx1 = fmaxf(mx1, __shfl_xor_sync(0xffffffffu, mx1, 1));
            mx1 = fmaxf(mx1, __shfl_xor_sync(0xffffffffu, mx1, 2));
            float nm0 = fmaxf(m0, mx0), nm1 = fmaxf(m1, mx1);
            float c0 = __expf(m0 - nm0), c1 = __expf(m1 - nm1);
            float sum0 = 0.f, sum1 = 0.f;
#pragma unroll
            for (int nt = 0; nt < 4; nt++) {
                s[nt][0] = __expf(s[nt][0] - nm0);
                s[nt][1] = __expf(s[nt][1] - nm0);
                s[nt][2] = __expf(s[nt][2] - nm1);
                s[nt][3] = __expf(s[nt][3] - nm1);
                sum0 += s[nt][0] + s[nt][1];
                sum1 += s[nt][2] + s[nt][3];
            }
            sum0 += __shfl_xor_sync(0xffffffffu, sum0, 1);
            sum0 += __shfl_xor_sync(0xffffffffu, sum0, 2);
            sum1 += __shfl_xor_sync(0xffffffffu, sum1, 1);
            sum1 += __shfl_xor_sync(0xffffffffu, sum1, 2);
            l0 = l0 * c0 + sum0;
            l1 = l1 * c1 + sum1;
#pragma unroll
            for (int nt = 0; nt < 8; nt++) {
                o[nt][0] *= c0; o[nt][1] *= c0;
                o[nt][2] *= c1; o[nt][3] *= c1;
            }
            m0 = nm0; m1 = nm1;

#pragma unroll
            for (int nt = 0; nt < 4; nt++) {
                uint2 p0; p0.x = tf32r(s[nt][0]); p0.y = tf32r(s[nt][1]);
                *(uint2*)(Pw + g * PSTR + nt * 8 + 2 * t) = p0;
                uint2 p1; p1.x = tf32r(s[nt][2]); p1.y = tf32r(s[nt][3]);
                *(uint2*)(Pw + (g + 8) * PSTR + nt * 8 + 2 * t) = p1;
            }
            __syncwarp();

#pragma unroll
            for (int ks = 0; ks < 4; ks++) {
                uint32_t ap[4];
                ap[0] = Pw[g * PSTR + ks * 8 + t];
                ap[1] = Pw[(g + 8) * PSTR + ks * 8 + t];
                ap[2] = Pw[g * PSTR + ks * 8 + t + 4];
                ap[3] = Pw[(g + 8) * PSTR + ks * 8 + t + 4];
#pragma unroll
                for (int nt = 0; nt < 8; nt++) {
                    uint32_t bf[2];
                    bf[0] = Vst[(sub * 32 + ks * 8 + t) * VSTR + nt * 8 + g];
                    bf[1] = Vst[(sub * 32 + ks * 8 + t + 4) * VSTR + nt * 8 + g];
                    mma_tf32(o[nt], ap, bf);
                }
            }
            __syncwarp();
        }
    }

    float i0 = 1.f / l0, i1 = 1.f / l1;
    __half* ob = out + ((size_t)(b * Sq + q0)) * Dq + h * HDq;
#pragma unroll
    for (int nt = 0; nt < 8; nt++) {
        *(__half2*)(ob + (size_t)g * Dq + nt * 8 + 2 * t) =
            __floats2half2_rn(o[nt][0] * i0, o[nt][1] * i0);
        *(__half2*)(ob + (size_t)(g + 8) * Dq + nt * 8 + 2 * t) =
            __floats2half2_rn(o[nt][2] * i1, o[nt][3] * i1);
    }
}

// ================= launch =================
extern "C" void kernel_launch(void* const* d_in, const int* in_sizes, int n_in,
                              void* d_out, int out_size) {
    const float* x     = (const float*)d_in[0];
    const float* Wq    = (const float*)d_in[1];
    const float* bq    = (const float*)d_in[2];
    const float* Wk    = (const float*)d_in[3];
    const float* bk    = (const float*)d_in[4];
    const float* Wv    = (const float*)d_in[5];
    const float* bv    = (const float*)d_in[6];
    const float* Wo    = (const float*)d_in[7];
    const float* bo    = (const float*)d_in[8];
    const float* ln1_g = (const float*)d_in[9];
    const float* ln1_b = (const float*)d_in[10];
    const float* W1    = (const float*)d_in[11];
    const float* b1    = (const float*)d_in[12];
    const float* W2    = (const float*)d_in[13];
    const float* b2    = (const float*)d_in[14];
    const float* ln2_g = (const float*)d_in[15];
    const float* ln2_b = (const float*)d_in[16];
    float* out = (float*)d_out;

    __half *h, *att, *h2, *mlp, *wq, *wk, *wv, *wo, *w1, *w2;
    float *q, *k, *v, *x2;
    cudaGetSymbolAddress((void**)&h,   g_h);
    cudaGetSymbolAddress((void**)&q,   g_q);
    cudaGetSymbolAddress((void**)&k,   g_k);
    cudaGetSymbolAddress((void**)&v,   g_v);
    cudaGetSymbolAddress((void**)&att, g_att);
    cudaGetSymbolAddress((void**)&x2,  g_x2);
    cudaGetSymbolAddress((void**)&h2,  g_h2);
    cudaGetSymbolAddress((void**)&mlp, g_mlp);
    cudaGetSymbolAddress((void**)&wq,  g_wq);
    cudaGetSymbolAddress((void**)&wk,  g_wk);
    cudaGetSymbolAddress((void**)&wv,  g_wv);
    cudaGetSymbolAddress((void**)&wo,  g_wo);
    cudaGetSymbolAddress((void**)&w1,  g_w1);
    cudaGetSymbolAddress((void**)&w2,  g_w2);

    cudaFuncSetAttribute(gemm_mma<0>, cudaFuncAttributeMaxDynamicSharedMemorySize, GEMM_SMEM);
    cudaFuncSetAttribute(gemm_mma<1>, cudaFuncAttributeMaxDynamicSharedMemorySize, GEMM_SMEM);
    cudaFuncSetAttribute(gemm_mma<2>, cudaFuncAttributeMaxDynamicSharedMemorySize, GEMM_SMEM);
    cudaFuncSetAttribute(attn_mma, cudaFuncAttributeMaxDynamicSharedMemorySize, ATT_SMEM);

    // 0) convert weights to fp16
    const int WTOT4 = (4 * Dq * Dq + 2 * Fq * Dq) / 4;
    wcvt_kernel<<<WTOT4 / 256, 256>>>(Wq, Wk, Wv, Wo, W1, W2, wq, wk, wv, wo, w1, w2);

    // 1) LN1 -> h (half)
    ln_kernel<<<NTOK, 256>>>(x, ln1_g, ln1_b, h);

    // 2) QKV (fp16 in, float tf32-rounded out)
    dim3 gqkv(Dq / 128, NTOK / 128);
    gemm_mma<0><<<gqkv, 256, GEMM_SMEM>>>(h, wq, bq, nullptr, q, NTOK, Dq, Dq);
    gemm_mma<0><<<gqkv, 256, GEMM_SMEM>>>(h, wk, bk, nullptr, k, NTOK, Dq, Dq);
    gemm_mma<0><<<gqkv, 256, GEMM_SMEM>>>(h, wv, bv, nullptr, v, NTOK, Dq, Dq);

    // 3) attention (tf32) -> att (half)
    dim3 gattn(Bq * Hq, Sq / 128);
    attn_mma<<<gattn, 256, ATT_SMEM>>>(q, k, v, att);

    // 4) output projection + residual -> x2 (float)
    gemm_mma<2><<<gqkv, 256, GEMM_SMEM>>>(att, wo, bo, x, x2, NTOK, Dq, Dq);

    // 5) LN2 -> h2 (half)
    ln_kernel<<<NTOK, 256>>>(x2, ln2_g, ln2_b, h2);

    // 6) MLP up + gelu -> mlp (half)
    dim3 g1(Fq / 128, NTOK / 128);
    gemm_mma<1><<<g1, 256, GEMM_SMEM>>>(h2, w1, b1, nullptr, mlp, NTOK, Fq, Dq);

    // 7) MLP down + residual -> out (float)
    dim3 g2(Dq / 128, NTOK / 128);
    gemm_mma<2><<<g2, 256, GEMM_SMEM>>>(mlp, w2, b2, x2, out, NTOK, Dq, Fq);
}